// round 2
// baseline (speedup 1.0000x reference)
#include <cuda_runtime.h>
#include <cuda_fp16.h>

// Multi-level hash-grid encoding, GB300 sm_103a. Round 2:
// fp16 (scaled) smem tables: gathers are LDS.32 instead of LDS.64 (halves
// smem bank-conflict wavefronts), table is 64KB -> 2 CTAs/SM (occ 24.5->49%).
// Entries uniform(+-1e-4) are scaled by 8192 into fp16 normal range
// (rel err ~1e-4 per entry); the scale is undone once per output.

#define NLV 16
#define TBL 16384          // max table rows per level (padded stacking)
#define BT  512            // threads per block
#define NCHUNK 37          // 16*37 = 592 blocks = 2 waves at 2 CTAs/SM
#define EMB_SCALE 8192.0f
#define EMB_INV   (1.0f / 8192.0f)

__constant__ int c_res[NLV]  = {16, 20, 25, 32, 40, 50, 64, 80,
                                101, 128, 161, 203, 256, 322, 406, 512};
__constant__ int c_nenc[NLV] = {4096, 8000, 15625, 16384, 16384, 16384, 16384, 16384,
                                16384, 16384, 16384, 16384, 16384, 16384, 16384, 16384};

__global__ __launch_bounds__(BT, 2)
void hashenc_kernel(const float* __restrict__ x,
                    const float* __restrict__ emb,
                    float2* __restrict__ out,
                    int npts, int ppb)
{
    const int level    = blockIdx.x;
    const int res      = c_res[level];
    const int nenc     = c_nenc[level];
    const bool hashing = (level >= 3);

    extern __shared__ __half2 tab[];
    const float2* src = reinterpret_cast<const float2*>(emb) + level * TBL;
    for (int i = threadIdx.x; i < nenc; i += BT) {
        const float2 v = __ldg(src + i);
        tab[i] = __floats2half2_rn(v.x * EMB_SCALE, v.y * EMB_SCALE);
    }
    __syncthreads();

    const float resf = (float)res;
    const int b0 = blockIdx.y * ppb;
    const int b1 = min(npts, b0 + ppb);

    for (int b = b0 + (int)threadIdx.x; b < b1; b += BT) {
        const float px = x[3 * b + 0];
        const float py = x[3 * b + 1];
        const float pz = x[3 * b + 2];

        const float sx = (px + 1.0f) * resf * 0.5f - 0.5f;
        const float sy = (py + 1.0f) * resf * 0.5f - 0.5f;
        const float sz = (pz + 1.0f) * resf * 0.5f - 0.5f;
        const float flx = floorf(sx), fly = floorf(sy), flz = floorf(sz);
        const float fx = sx - flx, fy = sy - fly, fz = sz - flz;
        const int cx = (int)flx, cy = (int)fly, cz = (int)flz;

        // per-dim weights with boundary masking folded in
        const float wx0 = (cx >= 0)       ? 1.0f - fx : 0.0f;
        const float wx1 = (cx <  res - 1) ? fx        : 0.0f;
        const float wy0 = (cy >= 0)       ? 1.0f - fy : 0.0f;
        const float wy1 = (cy <  res - 1) ? fy        : 0.0f;
        const float wz0 = (cz >= 0)       ? 1.0f - fz : 0.0f;
        const float wz1 = (cz <  res - 1) ? fz        : 0.0f;

        const float w00 = wx0 * wy0, w01 = wx0 * wy1;
        const float w10 = wx1 * wy0, w11 = wx1 * wy1;

        unsigned id[8];
        if (hashing) {
            const unsigned hx0 = (unsigned)cx;
            const unsigned hx1 = (unsigned)(cx + 1);
            const unsigned hy0 = (unsigned)cy       * 2654435761u;
            const unsigned hy1 = (unsigned)(cy + 1) * 2654435761u;
            const unsigned hz0 = (unsigned)cz       * 805459861u;
            const unsigned hz1 = (unsigned)(cz + 1) * 805459861u;
            const unsigned g00 = hx0 ^ hy0, g01 = hx0 ^ hy1;
            const unsigned g10 = hx1 ^ hy0, g11 = hx1 ^ hy1;
            const unsigned m = (unsigned)(nenc - 1);   // 16383
            id[0] = (g00 ^ hz0) & m;  id[1] = (g00 ^ hz1) & m;
            id[2] = (g01 ^ hz0) & m;  id[3] = (g01 ^ hz1) & m;
            id[4] = (g10 ^ hz0) & m;  id[5] = (g10 ^ hz1) & m;
            id[6] = (g11 ^ hz0) & m;  id[7] = (g11 ^ hz1) & m;
        } else {
            // ravel: valid ids < res^3 == nenc; invalid corners have weight 0,
            // so just clamp into range for a safe smem read.
            const int r2 = res * res;
            const int a0 = cx,        a1 = cx + 1;
            const int b0v = cy * res, b1v = (cy + 1) * res;
            const int c0v = cz * r2,  c1v = (cz + 1) * r2;
            const unsigned lim = (unsigned)(nenc - 1);
            id[0] = min((unsigned)(a0 + b0v + c0v), lim);
            id[1] = min((unsigned)(a0 + b0v + c1v), lim);
            id[2] = min((unsigned)(a0 + b1v + c0v), lim);
            id[3] = min((unsigned)(a0 + b1v + c1v), lim);
            id[4] = min((unsigned)(a1 + b0v + c0v), lim);
            id[5] = min((unsigned)(a1 + b0v + c1v), lim);
            id[6] = min((unsigned)(a1 + b1v + c0v), lim);
            id[7] = min((unsigned)(a1 + b1v + c1v), lim);
        }

        const float w[8] = { w00 * wz0, w00 * wz1, w01 * wz0, w01 * wz1,
                             w10 * wz0, w10 * wz1, w11 * wz0, w11 * wz1 };

        float ax = 0.0f, ay = 0.0f;
        #pragma unroll
        for (int k = 0; k < 8; k++) {
            const float2 e = __half22float2(tab[id[k]]);
            ax = fmaf(w[k], e.x, ax);
            ay = fmaf(w[k], e.y, ay);
        }

        out[b * NLV + level] = make_float2(ax * EMB_INV, ay * EMB_INV);
    }
}

extern "C" void kernel_launch(void* const* d_in, const int* in_sizes, int n_in,
                              void* d_out, int out_size)
{
    const float* x   = (const float*)d_in[0];   // (B, 3) float32
    const float* emb = (const float*)d_in[1];   // (16, 16384, 2) float32
    float2* out      = (float2*)d_out;          // (B, 16, 2) float32

    const int npts = in_sizes[0] / 3;
    const int ppb  = (npts + NCHUNK - 1) / NCHUNK;
    const int smem = TBL * (int)sizeof(__half2); // 64 KB

    cudaFuncSetAttribute(hashenc_kernel,
                         cudaFuncAttributeMaxDynamicSharedMemorySize, smem);

    hashenc_kernel<<<dim3(NLV, NCHUNK), BT, smem>>>(x, emb, out, npts, ppb);
}

// round 4
// speedup vs baseline: 1.0745x; 1.0745x over previous
#include <cuda_runtime.h>
#include <cuda_fp16.h>

// Round 3: two-kernel split.
// K1 (hashenc): R1's proven fp32-smem-table gather kernel, but stores scaled
//   fp16x2 results to a (level, point) scratch -> coalesced stores (1 wf per
//   warp-store instead of 32: out[b*16+lvl] strided 8B/128B was 16M wavefronts).
// K2 (transpose): (L,B) half2 scratch -> (B,L,2) fp32 output, smem-tiled,
//   coalesced both sides, DRAM-bound.
// Only the final blended output is quantized to fp16 (scaled x8192 into the
// fp16 normal range); R2 measured ~2e-4 rel_err for fp16 quantization.

#define NLV 16
#define TBL 16384          // max table rows per level (padded stacking)
#define BT  512            // threads per block (K1)
#define NCHUNK 37          // 16*37 = 592 blocks
#define MAXB 1048576
#define SC  8192.0f
#define SCI (1.0f / 8192.0f)
#define TP  256            // transpose tile: points per block == threads

__device__ __half2 g_scr[NLV * MAXB];   // 64 MB scratch, layout (level, point)

__constant__ int c_res[NLV]  = {16, 20, 25, 32, 40, 50, 64, 80,
                                101, 128, 161, 203, 256, 322, 406, 512};
__constant__ int c_nenc[NLV] = {4096, 8000, 15625, 16384, 16384, 16384, 16384, 16384,
                                16384, 16384, 16384, 16384, 16384, 16384, 16384, 16384};

__global__ __launch_bounds__(BT, 1)
void hashenc_kernel(const float* __restrict__ x,
                    const float* __restrict__ emb,
                    int npts, int ppb)
{
    const int level    = blockIdx.x;
    const int res      = c_res[level];
    const int nenc     = c_nenc[level];
    const bool hashing = (level >= 3);

    extern __shared__ float2 tab[];
    const float2* src = reinterpret_cast<const float2*>(emb) + level * TBL;
    for (int i = threadIdx.x; i < nenc; i += BT)
        tab[i] = __ldg(src + i);
    __syncthreads();

    const float resf = (float)res;
    const int b0 = blockIdx.y * ppb;
    const int b1 = min(npts, b0 + ppb);
    __half2* scr = g_scr + level * npts;

    for (int b = b0 + (int)threadIdx.x; b < b1; b += BT) {
        const float px = x[3 * b + 0];
        const float py = x[3 * b + 1];
        const float pz = x[3 * b + 2];

        // grid coords: s in [-0.5, res-0.5], c in [-1, res-1]
        const float sx = (px + 1.0f) * resf * 0.5f - 0.5f;
        const float sy = (py + 1.0f) * resf * 0.5f - 0.5f;
        const float sz = (pz + 1.0f) * resf * 0.5f - 0.5f;
        const float flx = floorf(sx), fly = floorf(sy), flz = floorf(sz);
        const float fx = sx - flx, fy = sy - fly, fz = sz - flz;
        const int cx = (int)flx, cy = (int)fly, cz = (int)flz;

        // per-dim weights with boundary masking folded in:
        // offset 0 valid iff c >= 0; offset 1 valid iff c+1 < res
        const float wx0 = (cx >= 0)       ? 1.0f - fx : 0.0f;
        const float wx1 = (cx <  res - 1) ? fx        : 0.0f;
        const float wy0 = (cy >= 0)       ? 1.0f - fy : 0.0f;
        const float wy1 = (cy <  res - 1) ? fy        : 0.0f;
        const float wz0 = (cz >= 0)       ? 1.0f - fz : 0.0f;
        const float wz1 = (cz <  res - 1) ? fz        : 0.0f;

        const float w00 = wx0 * wy0, w01 = wx0 * wy1;
        const float w10 = wx1 * wy0, w11 = wx1 * wy1;

        unsigned id[8];
        if (hashing) {
            // h = c0 ^ (c1*2654435761) ^ (c2*805459861), uint32 wrap; nenc = 2^14
            const unsigned hx0 = (unsigned)cx;
            const unsigned hx1 = (unsigned)(cx + 1);
            const unsigned hy0 = (unsigned)cy       * 2654435761u;
            const unsigned hy1 = (unsigned)(cy + 1) * 2654435761u;
            const unsigned hz0 = (unsigned)cz       * 805459861u;
            const unsigned hz1 = (unsigned)(cz + 1) * 805459861u;
            const unsigned g00 = hx0 ^ hy0, g01 = hx0 ^ hy1;
            const unsigned g10 = hx1 ^ hy0, g11 = hx1 ^ hy1;
            const unsigned m = (unsigned)(nenc - 1);   // 16383
            id[0] = (g00 ^ hz0) & m;  id[1] = (g00 ^ hz1) & m;
            id[2] = (g01 ^ hz0) & m;  id[3] = (g01 ^ hz1) & m;
            id[4] = (g10 ^ hz0) & m;  id[5] = (g10 ^ hz1) & m;
            id[6] = (g11 ^ hz0) & m;  id[7] = (g11 ^ hz1) & m;
        } else {
            // ravel: valid ids < res^3 == nenc; invalid corners have weight 0,
            // just clamp into range for a safe smem read.
            const int r2 = res * res;
            const int a0 = cx,        a1 = cx + 1;
            const int b0v = cy * res, b1v = (cy + 1) * res;
            const int c0v = cz * r2,  c1v = (cz + 1) * r2;
            const unsigned lim = (unsigned)(nenc - 1);
            id[0] = min((unsigned)(a0 + b0v + c0v), lim);
            id[1] = min((unsigned)(a0 + b0v + c1v), lim);
            id[2] = min((unsigned)(a0 + b1v + c0v), lim);
            id[3] = min((unsigned)(a0 + b1v + c1v), lim);
            id[4] = min((unsigned)(a1 + b0v + c0v), lim);
            id[5] = min((unsigned)(a1 + b0v + c1v), lim);
            id[6] = min((unsigned)(a1 + b1v + c0v), lim);
            id[7] = min((unsigned)(a1 + b1v + c1v), lim);
        }

        const float w[8] = { w00 * wz0, w00 * wz1, w01 * wz0, w01 * wz1,
                             w10 * wz0, w10 * wz1, w11 * wz0, w11 * wz1 };

        float ax = 0.0f, ay = 0.0f;
        #pragma unroll
        for (int k = 0; k < 8; k++) {
            const float2 e = tab[id[k]];
            ax = fmaf(w[k], e.x, ax);
            ay = fmaf(w[k], e.y, ay);
        }

        // coalesced (level, point) scratch store, scaled into fp16 normal range
        scr[b] = __floats2half2_rn(ax * SC, ay * SC);
    }
}

// (L,B) half2 -> (B,L,2) fp32 transpose, smem tiled, coalesced both sides.
__global__ __launch_bounds__(TP)
void transpose_kernel(float4* __restrict__ out, int npts)
{
    __shared__ __half2 tile[NLV][TP + 2];   // stride 258: conflict-free both phases

    const int b0 = blockIdx.x * TP;
    const int t  = threadIdx.x;

    // load: 16 coalesced rows from scratch
    const int b = b0 + t;
    #pragma unroll
    for (int l = 0; l < NLV; l++)
        tile[l][t] = (b < npts) ? g_scr[l * npts + b] : __floats2half2_rn(0.f, 0.f);
    __syncthreads();

    // write: tile's output region is contiguous [b0*16, (b0+TP)*16) float2
    // = TP*8 float4. float4 i -> point p = i/8, level pair jp = i%8.
    float4* obase = out + (size_t)b0 * 8;
    const int nf4 = TP * 8;
    #pragma unroll 4
    for (int i = t; i < nf4; i += TP) {
        const int p  = i >> 3;
        const int jp = i & 7;
        if (b0 + p < npts) {
            const float2 e0 = __half22float2(tile[2 * jp][p]);
            const float2 e1 = __half22float2(tile[2 * jp + 1][p]);
            obase[i] = make_float4(e0.x * SCI, e0.y * SCI, e1.x * SCI, e1.y * SCI);
        }
    }
}

extern "C" void kernel_launch(void* const* d_in, const int* in_sizes, int n_in,
                              void* d_out, int out_size)
{
    const float* x   = (const float*)d_in[0];   // (B, 3) float32
    const float* emb = (const float*)d_in[1];   // (16, 16384, 2) float32
    float4* out      = (float4*)d_out;          // (B, 16, 2) float32

    const int npts = in_sizes[0] / 3;
    const int ppb  = (npts + NCHUNK - 1) / NCHUNK;
    const int smem = TBL * (int)sizeof(float2); // 128 KB

    cudaFuncSetAttribute(hashenc_kernel,
                         cudaFuncAttributeMaxDynamicSharedMemorySize, smem);

    hashenc_kernel<<<dim3(NLV, NCHUNK), BT, smem>>>(x, emb, npts, ppb);
    transpose_kernel<<<(npts + TP - 1) / TP, TP>>>(out, npts);
}

// round 5
// speedup vs baseline: 1.3931x; 1.2965x over previous
#include <cuda_runtime.h>

// Round 5: R1 structure (proven fastest: single kernel, fp32 smem tables,
// fused scatter stores) with BT 512 -> 1024. The 128KB table pins us to
// 1 CTA/SM; at 512 threads that is only 16 warps (occ 24.5%, L1=84%) and the
// smem crossbar starves between dependent 29-cyc LDS bursts. 32 warps/SM
// keeps the gather queue fed with zero added instructions.

#define NLV 16
#define TBL 16384          // max table rows per level (padded stacking)
#define BT  1024           // threads per block (32 warps, 1 CTA/SM)
#define NCHUNK 37          // 16*37 = 592 blocks = 4 exact waves on 148 SMs

__constant__ int c_res[NLV]  = {16, 20, 25, 32, 40, 50, 64, 80,
                                101, 128, 161, 203, 256, 322, 406, 512};
__constant__ int c_nenc[NLV] = {4096, 8000, 15625, 16384, 16384, 16384, 16384, 16384,
                                16384, 16384, 16384, 16384, 16384, 16384, 16384, 16384};

__global__ __launch_bounds__(BT, 1)
void hashenc_kernel(const float* __restrict__ x,
                    const float* __restrict__ emb,
                    float2* __restrict__ out,
                    int npts, int ppb)
{
    const int level    = blockIdx.x;
    const int res      = c_res[level];
    const int nenc     = c_nenc[level];
    const bool hashing = (level >= 3);

    extern __shared__ float2 tab[];
    const float2* src = reinterpret_cast<const float2*>(emb) + level * TBL;
    for (int i = threadIdx.x; i < nenc; i += BT)
        tab[i] = __ldg(src + i);
    __syncthreads();

    const float resf = (float)res;
    const int b0 = blockIdx.y * ppb;
    const int b1 = min(npts, b0 + ppb);

    for (int b = b0 + (int)threadIdx.x; b < b1; b += BT) {
        const float px = x[3 * b + 0];
        const float py = x[3 * b + 1];
        const float pz = x[3 * b + 2];

        // grid coords: s in [-0.5, res-0.5], c in [-1, res-1]
        const float sx = (px + 1.0f) * resf * 0.5f - 0.5f;
        const float sy = (py + 1.0f) * resf * 0.5f - 0.5f;
        const float sz = (pz + 1.0f) * resf * 0.5f - 0.5f;
        const float flx = floorf(sx), fly = floorf(sy), flz = floorf(sz);
        const float fx = sx - flx, fy = sy - fly, fz = sz - flz;
        const int cx = (int)flx, cy = (int)fly, cz = (int)flz;

        // per-dim weights with boundary masking folded in:
        // offset 0 valid iff c >= 0; offset 1 valid iff c+1 < res
        const float wx0 = (cx >= 0)       ? 1.0f - fx : 0.0f;
        const float wx1 = (cx <  res - 1) ? fx        : 0.0f;
        const float wy0 = (cy >= 0)       ? 1.0f - fy : 0.0f;
        const float wy1 = (cy <  res - 1) ? fy        : 0.0f;
        const float wz0 = (cz >= 0)       ? 1.0f - fz : 0.0f;
        const float wz1 = (cz <  res - 1) ? fz        : 0.0f;

        const float w00 = wx0 * wy0, w01 = wx0 * wy1;
        const float w10 = wx1 * wy0, w11 = wx1 * wy1;

        unsigned id[8];
        if (hashing) {
            // h = c0 ^ (c1*2654435761) ^ (c2*805459861), uint32 wrap; nenc = 2^14
            const unsigned hx0 = (unsigned)cx;
            const unsigned hx1 = (unsigned)(cx + 1);
            const unsigned hy0 = (unsigned)cy       * 2654435761u;
            const unsigned hy1 = (unsigned)(cy + 1) * 2654435761u;
            const unsigned hz0 = (unsigned)cz       * 805459861u;
            const unsigned hz1 = (unsigned)(cz + 1) * 805459861u;
            const unsigned g00 = hx0 ^ hy0, g01 = hx0 ^ hy1;
            const unsigned g10 = hx1 ^ hy0, g11 = hx1 ^ hy1;
            const unsigned m = (unsigned)(nenc - 1);   // 16383
            id[0] = (g00 ^ hz0) & m;  id[1] = (g00 ^ hz1) & m;
            id[2] = (g01 ^ hz0) & m;  id[3] = (g01 ^ hz1) & m;
            id[4] = (g10 ^ hz0) & m;  id[5] = (g10 ^ hz1) & m;
            id[6] = (g11 ^ hz0) & m;  id[7] = (g11 ^ hz1) & m;
        } else {
            // ravel: valid ids < res^3 == nenc; invalid corners have weight 0,
            // just clamp into range for a safe smem read.
            const int r2 = res * res;
            const int a0 = cx,        a1 = cx + 1;
            const int b0v = cy * res, b1v = (cy + 1) * res;
            const int c0v = cz * r2,  c1v = (cz + 1) * r2;
            const unsigned lim = (unsigned)(nenc - 1);
            id[0] = min((unsigned)(a0 + b0v + c0v), lim);
            id[1] = min((unsigned)(a0 + b0v + c1v), lim);
            id[2] = min((unsigned)(a0 + b1v + c0v), lim);
            id[3] = min((unsigned)(a0 + b1v + c1v), lim);
            id[4] = min((unsigned)(a1 + b0v + c0v), lim);
            id[5] = min((unsigned)(a1 + b0v + c1v), lim);
            id[6] = min((unsigned)(a1 + b1v + c0v), lim);
            id[7] = min((unsigned)(a1 + b1v + c1v), lim);
        }

        // weights in corner-offset order [[0,0,0],[0,0,1],...,[1,1,1]]
        const float w[8] = { w00 * wz0, w00 * wz1, w01 * wz0, w01 * wz1,
                             w10 * wz0, w10 * wz1, w11 * wz0, w11 * wz1 };

        float ax = 0.0f, ay = 0.0f;
        #pragma unroll
        for (int k = 0; k < 8; k++) {
            const float2 e = tab[id[k]];
            ax = fmaf(w[k], e.x, ax);
            ay = fmaf(w[k], e.y, ay);
        }

        out[b * NLV + level] = make_float2(ax, ay);
    }
}

extern "C" void kernel_launch(void* const* d_in, const int* in_sizes, int n_in,
                              void* d_out, int out_size)
{
    const float* x   = (const float*)d_in[0];   // (B, 3) float32
    const float* emb = (const float*)d_in[1];   // (16, 16384, 2) float32
    float2* out      = (float2*)d_out;          // (B, 16, 2) float32

    const int npts = in_sizes[0] / 3;
    const int ppb  = (npts + NCHUNK - 1) / NCHUNK;
    const int smem = TBL * (int)sizeof(float2); // 128 KB

    cudaFuncSetAttribute(hashenc_kernel,
                         cudaFuncAttributeMaxDynamicSharedMemorySize, smem);

    hashenc_kernel<<<dim3(NLV, NCHUNK), BT, smem>>>(x, emb, out, npts, ppb);
}

// round 6
// speedup vs baseline: 1.3934x; 1.0002x over previous
#include <cuda_runtime.h>

// Round 6: R5 base (fp32 smem tables, BT=1024, fused scatter stores) +
// x padded to float4 by a tiny pre-kernel. The main loop re-reads x 16x per
// point; as (B,3) that is 3 scalar LDG (~9 L1 wavefronts/warp-iter), as
// (B,4) it is one LDG.128 (~4 wf). Kernel is l1tex-throughput-bound
// (R5: 16->32 warps changed nothing), so wavefront removal is the only lever.

#define NLV 16
#define TBL 16384          // max table rows per level (padded stacking)
#define BT  1024           // threads per block (32 warps, 1 CTA/SM)
#define NCHUNK 37          // 16*37 = 592 blocks = 4 waves on 148 SMs
#define MAXB 1048576

__device__ float4 g_x4[MAXB];   // 16 MB padded coords

__constant__ int c_res[NLV]  = {16, 20, 25, 32, 40, 50, 64, 80,
                                101, 128, 161, 203, 256, 322, 406, 512};
__constant__ int c_nenc[NLV] = {4096, 8000, 15625, 16384, 16384, 16384, 16384, 16384,
                                16384, 16384, 16384, 16384, 16384, 16384, 16384, 16384};

// pad (B,3) -> (B,4): 4 points per thread, 3 coalesced float4 reads, 4 writes
__global__ __launch_bounds__(256)
void pad_kernel(const float4* __restrict__ x, int npts)
{
    const int q = blockIdx.x * 256 + threadIdx.x;   // quad index
    const int nq = npts >> 2;
    if (q < nq) {
        const float4 a = __ldg(x + 3 * q + 0);  // p0.xyz p1.x
        const float4 b = __ldg(x + 3 * q + 1);  // p1.yz  p2.xy
        const float4 c = __ldg(x + 3 * q + 2);  // p2.z   p3.xyz
        g_x4[4 * q + 0] = make_float4(a.x, a.y, a.z, 0.f);
        g_x4[4 * q + 1] = make_float4(a.w, b.x, b.y, 0.f);
        g_x4[4 * q + 2] = make_float4(b.z, b.w, c.x, 0.f);
        g_x4[4 * q + 3] = make_float4(c.y, c.z, c.w, 0.f);
    }
    // tail points (npts not multiple of 4)
    const int tail0 = (npts >> 2) << 2;
    const int t = tail0 + q;
    if (q < npts - tail0) {
        const float* xs = (const float*)x;
        g_x4[t] = make_float4(xs[3 * t], xs[3 * t + 1], xs[3 * t + 2], 0.f);
    }
}

__global__ __launch_bounds__(BT, 1)
void hashenc_kernel(const float* __restrict__ emb,
                    float2* __restrict__ out,
                    int npts, int ppb)
{
    const int level    = blockIdx.x;
    const int res      = c_res[level];
    const int nenc     = c_nenc[level];
    const bool hashing = (level >= 3);

    extern __shared__ float2 tab[];
    {   // float4 fill: two table rows per load
        float4* tab4 = reinterpret_cast<float4*>(tab);
        const float4* src4 = reinterpret_cast<const float4*>(emb) + level * (TBL / 2);
        const int n4 = (nenc + 1) >> 1;   // nenc even for all levels? 15625 is odd
        for (int i = threadIdx.x; i < n4; i += BT) {
            // safe: emb rows are padded to TBL per level, so reading one extra
            // float2 within the level's slab is in-bounds.
            tab4[i] = __ldg(src4 + i);
        }
    }
    __syncthreads();

    const float resf = (float)res;
    const int b0 = blockIdx.y * ppb;
    const int b1 = min(npts, b0 + ppb);

    for (int b = b0 + (int)threadIdx.x; b < b1; b += BT) {
        const float4 p = __ldg(&g_x4[b]);

        // grid coords: s in [-0.5, res-0.5], c in [-1, res-1]
        const float sx = (p.x + 1.0f) * resf * 0.5f - 0.5f;
        const float sy = (p.y + 1.0f) * resf * 0.5f - 0.5f;
        const float sz = (p.z + 1.0f) * resf * 0.5f - 0.5f;
        const float flx = floorf(sx), fly = floorf(sy), flz = floorf(sz);
        const float fx = sx - flx, fy = sy - fly, fz = sz - flz;
        const int cx = (int)flx, cy = (int)fly, cz = (int)flz;

        // per-dim weights with boundary masking folded in:
        // offset 0 valid iff c >= 0; offset 1 valid iff c+1 < res
        const float wx0 = (cx >= 0)       ? 1.0f - fx : 0.0f;
        const float wx1 = (cx <  res - 1) ? fx        : 0.0f;
        const float wy0 = (cy >= 0)       ? 1.0f - fy : 0.0f;
        const float wy1 = (cy <  res - 1) ? fy        : 0.0f;
        const float wz0 = (cz >= 0)       ? 1.0f - fz : 0.0f;
        const float wz1 = (cz <  res - 1) ? fz        : 0.0f;

        const float w00 = wx0 * wy0, w01 = wx0 * wy1;
        const float w10 = wx1 * wy0, w11 = wx1 * wy1;

        unsigned id[8];
        if (hashing) {
            // h = c0 ^ (c1*2654435761) ^ (c2*805459861), uint32 wrap; nenc = 2^14
            const unsigned hx0 = (unsigned)cx;
            const unsigned hx1 = (unsigned)(cx + 1);
            const unsigned hy0 = (unsigned)cy       * 2654435761u;
            const unsigned hy1 = (unsigned)(cy + 1) * 2654435761u;
            const unsigned hz0 = (unsigned)cz       * 805459861u;
            const unsigned hz1 = (unsigned)(cz + 1) * 805459861u;
            const unsigned g00 = hx0 ^ hy0, g01 = hx0 ^ hy1;
            const unsigned g10 = hx1 ^ hy0, g11 = hx1 ^ hy1;
            const unsigned m = (unsigned)(nenc - 1);   // 16383
            id[0] = (g00 ^ hz0) & m;  id[1] = (g00 ^ hz1) & m;
            id[2] = (g01 ^ hz0) & m;  id[3] = (g01 ^ hz1) & m;
            id[4] = (g10 ^ hz0) & m;  id[5] = (g10 ^ hz1) & m;
            id[6] = (g11 ^ hz0) & m;  id[7] = (g11 ^ hz1) & m;
        } else {
            // ravel: valid ids < res^3 == nenc; invalid corners have weight 0,
            // just clamp into range for a safe smem read.
            const int r2 = res * res;
            const int a0 = cx,        a1 = cx + 1;
            const int b0v = cy * res, b1v = (cy + 1) * res;
            const int c0v = cz * r2,  c1v = (cz + 1) * r2;
            const unsigned lim = (unsigned)(nenc - 1);
            id[0] = min((unsigned)(a0 + b0v + c0v), lim);
            id[1] = min((unsigned)(a0 + b0v + c1v), lim);
            id[2] = min((unsigned)(a0 + b1v + c0v), lim);
            id[3] = min((unsigned)(a0 + b1v + c1v), lim);
            id[4] = min((unsigned)(a1 + b0v + c0v), lim);
            id[5] = min((unsigned)(a1 + b0v + c1v), lim);
            id[6] = min((unsigned)(a1 + b1v + c0v), lim);
            id[7] = min((unsigned)(a1 + b1v + c1v), lim);
        }

        // weights in corner-offset order [[0,0,0],[0,0,1],...,[1,1,1]]
        const float w[8] = { w00 * wz0, w00 * wz1, w01 * wz0, w01 * wz1,
                             w10 * wz0, w10 * wz1, w11 * wz0, w11 * wz1 };

        float ax = 0.0f, ay = 0.0f;
        #pragma unroll
        for (int k = 0; k < 8; k++) {
            const float2 e = tab[id[k]];
            ax = fmaf(w[k], e.x, ax);
            ay = fmaf(w[k], e.y, ay);
        }

        out[b * NLV + level] = make_float2(ax, ay);
    }
}

extern "C" void kernel_launch(void* const* d_in, const int* in_sizes, int n_in,
                              void* d_out, int out_size)
{
    const float* x   = (const float*)d_in[0];   // (B, 3) float32
    const float* emb = (const float*)d_in[1];   // (16, 16384, 2) float32
    float2* out      = (float2*)d_out;          // (B, 16, 2) float32

    const int npts = in_sizes[0] / 3;
    const int ppb  = (npts + NCHUNK - 1) / NCHUNK;
    const int smem = TBL * (int)sizeof(float2); // 128 KB

    cudaFuncSetAttribute(hashenc_kernel,
                         cudaFuncAttributeMaxDynamicSharedMemorySize, smem);

    const int nq = (npts + 3) / 4;
    pad_kernel<<<(nq + 255) / 256, 256>>>((const float4*)x, npts);
    hashenc_kernel<<<dim3(NLV, NCHUNK), BT, smem>>>(emb, out, npts, ppb);
}

// round 9
// speedup vs baseline: 1.8197x; 1.3060x over previous
#include <cuda_runtime.h>
#include <cuda_fp16.h>

// Round 7: clean A/B on the scattered-store term at 32 warps.
// K1 = R5's proven gather kernel (fp32 smem tables, BT=1024, 1 CTA/SM) with
//   the ONLY change being the store: scattered out[b*16+lvl] (32 lines/warp)
//   -> coalesced fp16x2 scratch in (L,B) layout (1 line/warp).
// K2 = (L,B) half2 -> (B,16,2) fp32 transpose, bank-conflict-free smem tile,
//   vectorized loads/stores. Scratch (64MB) is L2-warm from K1.
// Output quantized once to scaled fp16 (x8192 -> normal range): rel_err
// ~2.1e-4, measured in R2/R3.

#define NLV 16
#define TBL 16384
#define BT  1024           // 32 warps, 1 CTA/SM (128KB table)
#define NCHUNK 37          // 16*37 = 592 blocks
#define MAXB 1048576
#define SC   8192.0f
#define SCI  (1.0f / 8192.0f)

__device__ __half2 g_scr[NLV * MAXB];   // 64 MB, layout (level, point)

__constant__ int c_res[NLV]  = {16, 20, 25, 32, 40, 50, 64, 80,
                                101, 128, 161, 203, 256, 322, 406, 512};
__constant__ int c_nenc[NLV] = {4096, 8000, 15625, 16384, 16384, 16384, 16384, 16384,
                                16384, 16384, 16384, 16384, 16384, 16384, 16384, 16384};

__global__ __launch_bounds__(BT, 1)
void hashenc_kernel(const float* __restrict__ x,
                    const float* __restrict__ emb,
                    int npts, int ppb)
{
    const int level    = blockIdx.x;
    const int res      = c_res[level];
    const int nenc     = c_nenc[level];
    const bool hashing = (level >= 3);

    extern __shared__ float2 tab[];
    const float2* src = reinterpret_cast<const float2*>(emb) + level * TBL;
    for (int i = threadIdx.x; i < nenc; i += BT)
        tab[i] = __ldg(src + i);
    __syncthreads();

    const float resf = (float)res;
    const int b0 = blockIdx.y * ppb;
    const int b1 = min(npts, b0 + ppb);
    __half2* scr = g_scr + (size_t)level * npts;

    for (int b = b0 + (int)threadIdx.x; b < b1; b += BT) {
        const float px = x[3 * b + 0];
        const float py = x[3 * b + 1];
        const float pz = x[3 * b + 2];

        const float sx = (px + 1.0f) * resf * 0.5f - 0.5f;
        const float sy = (py + 1.0f) * resf * 0.5f - 0.5f;
        const float sz = (pz + 1.0f) * resf * 0.5f - 0.5f;
        const float flx = floorf(sx), fly = floorf(sy), flz = floorf(sz);
        const float fx = sx - flx, fy = sy - fly, fz = sz - flz;
        const int cx = (int)flx, cy = (int)fly, cz = (int)flz;

        const float wx0 = (cx >= 0)       ? 1.0f - fx : 0.0f;
        const float wx1 = (cx <  res - 1) ? fx        : 0.0f;
        const float wy0 = (cy >= 0)       ? 1.0f - fy : 0.0f;
        const float wy1 = (cy <  res - 1) ? fy        : 0.0f;
        const float wz0 = (cz >= 0)       ? 1.0f - fz : 0.0f;
        const float wz1 = (cz <  res - 1) ? fz        : 0.0f;

        const float w00 = wx0 * wy0, w01 = wx0 * wy1;
        const float w10 = wx1 * wy0, w11 = wx1 * wy1;

        unsigned id[8];
        if (hashing) {
            const unsigned hx0 = (unsigned)cx;
            const unsigned hx1 = (unsigned)(cx + 1);
            const unsigned hy0 = (unsigned)cy       * 2654435761u;
            const unsigned hy1 = (unsigned)(cy + 1) * 2654435761u;
            const unsigned hz0 = (unsigned)cz       * 805459861u;
            const unsigned hz1 = (unsigned)(cz + 1) * 805459861u;
            const unsigned g00 = hx0 ^ hy0, g01 = hx0 ^ hy1;
            const unsigned g10 = hx1 ^ hy0, g11 = hx1 ^ hy1;
            const unsigned m = (unsigned)(nenc - 1);
            id[0] = (g00 ^ hz0) & m;  id[1] = (g00 ^ hz1) & m;
            id[2] = (g01 ^ hz0) & m;  id[3] = (g01 ^ hz1) & m;
            id[4] = (g10 ^ hz0) & m;  id[5] = (g10 ^ hz1) & m;
            id[6] = (g11 ^ hz0) & m;  id[7] = (g11 ^ hz1) & m;
        } else {
            const int r2 = res * res;
            const int a0 = cx,        a1 = cx + 1;
            const int b0v = cy * res, b1v = (cy + 1) * res;
            const int c0v = cz * r2,  c1v = (cz + 1) * r2;
            const unsigned lim = (unsigned)(nenc - 1);
            id[0] = min((unsigned)(a0 + b0v + c0v), lim);
            id[1] = min((unsigned)(a0 + b0v + c1v), lim);
            id[2] = min((unsigned)(a0 + b1v + c0v), lim);
            id[3] = min((unsigned)(a0 + b1v + c1v), lim);
            id[4] = min((unsigned)(a1 + b0v + c0v), lim);
            id[5] = min((unsigned)(a1 + b0v + c1v), lim);
            id[6] = min((unsigned)(a1 + b1v + c0v), lim);
            id[7] = min((unsigned)(a1 + b1v + c1v), lim);
        }

        const float w[8] = { w00 * wz0, w00 * wz1, w01 * wz0, w01 * wz1,
                             w10 * wz0, w10 * wz1, w11 * wz0, w11 * wz1 };

        float ax = 0.0f, ay = 0.0f;
        #pragma unroll
        for (int k = 0; k < 8; k++) {
            const float2 e = tab[id[k]];
            ax = fmaf(w[k], e.x, ax);
            ay = fmaf(w[k], e.y, ay);
        }

        // coalesced (level, point) store, scaled into fp16 normal range
        scr[b] = __floats2half2_rn(ax * SC, ay * SC);
    }
}

// (L,B) half2 -> (B,16,2) fp32. Tile 512 points. Smem row stride 514 half2:
// 514 mod 32 = 2 -> both read patterns below are bank-conflict-free.
#define TPP 512
#define KT  256
#define TSTR 514

__global__ __launch_bounds__(KT)
void transpose_kernel(float4* __restrict__ out, int npts)
{
    __shared__ __half2 tile[NLV * TSTR];

    const int b0 = blockIdx.x * TPP;
    const int t  = threadIdx.x;
    const bool full = (b0 + TPP <= npts);

    if (full) {
        // 16 rows x 128 uint4 (4 points each); g_scr row base 16B-aligned
        // (b0 multiple of 512, half2 = 4B).
        #pragma unroll 4
        for (int idx = t; idx < NLV * (TPP / 4); idx += KT) {
            const int l = idx >> 7;        // / (TPP/4)
            const int j = idx & 127;
            const uint4 v = *reinterpret_cast<const uint4*>(
                &g_scr[(size_t)l * npts + b0 + 4 * j]);
            uint2* dst = reinterpret_cast<uint2*>(&tile[l * TSTR + 4 * j]);
            dst[0] = make_uint2(v.x, v.y);
            dst[1] = make_uint2(v.z, v.w);
        }
    } else {
        for (int idx = t; idx < NLV * TPP; idx += KT) {
            const int l = idx >> 9;
            const int p = idx & (TPP - 1);
            tile[l * TSTR + p] = (b0 + p < npts)
                ? g_scr[(size_t)l * npts + b0 + p]
                : __floats2half2_rn(0.f, 0.f);
        }
    }
    __syncthreads();

    // out region for the tile: contiguous TPP*8 float4.
    // i -> point p = i>>3, level pair jp = i&7 (levels 2jp, 2jp+1).
    float4* obase = out + (size_t)b0 * 8;
    #pragma unroll 4
    for (int i = t; i < TPP * 8; i += KT) {
        const int p  = i >> 3;
        const int jp = i & 7;
        if (full || b0 + p < npts) {
            const float2 e0 = __half22float2(tile[(2 * jp)     * TSTR + p]);
            const float2 e1 = __half22float2(tile[(2 * jp + 1) * TSTR + p]);
            obase[i] = make_float4(e0.x * SCI, e0.y * SCI, e1.x * SCI, e1.y * SCI);
        }
    }
}

extern "C" void kernel_launch(void* const* d_in, const int* in_sizes, int n_in,
                              void* d_out, int out_size)
{
    const float* x   = (const float*)d_in[0];   // (B, 3) float32
    const float* emb = (const float*)d_in[1];   // (16, 16384, 2) float32
    float4* out      = (float4*)d_out;          // (B, 16, 2) float32

    const int npts = in_sizes[0] / 3;
    const int ppb  = (npts + NCHUNK - 1) / NCHUNK;
    const int smem = TBL * (int)sizeof(float2); // 128 KB

    cudaFuncSetAttribute(hashenc_kernel,
                         cudaFuncAttributeMaxDynamicSharedMemorySize, smem);

    hashenc_kernel<<<dim3(NLV, NCHUNK), BT, smem>>>(x, emb, npts, ppb);
    transpose_kernel<<<(npts + TPP - 1) / TPP, KT>>>(out, npts);
}

// round 10
// speedup vs baseline: 2.0383x; 1.1201x over previous
#include <cuda_runtime.h>
#include <cuda_fp16.h>

// Round 10: R7/R9 structure (coalesced fp16 scratch store + transpose K2),
// single change: smem table float2 -> scaled half2.
// Bank model: LDS.64 gather = 2 phases x 16 lanes over 16 bank-pairs
// (~6.4 cyc); LDS.32 gather = 32 lanes over 32 banks (~3.4 cyc).
// 8 gathers/point-level -> ~24 cyc/warp-iter saved on the binding l1tex pipe.
// Scale (x8192) folded into table fill; hot loop loses 2 FMULs, gains 8 H2F
// converts (idle fma pipe). Expected rel_err ~3e-4 (table + scratch quant).

#define NLV 16
#define TBL 16384
#define BT  1024           // 32 warps, 1 CTA/SM
#define NCHUNK 37          // 16*37 = 592 blocks
#define MAXB 1048576
#define SC   8192.0f
#define SCI  (1.0f / 8192.0f)

__device__ __half2 g_scr[NLV * MAXB];   // 64 MB, layout (level, point)

__constant__ int c_res[NLV]  = {16, 20, 25, 32, 40, 50, 64, 80,
                                101, 128, 161, 203, 256, 322, 406, 512};
__constant__ int c_nenc[NLV] = {4096, 8000, 15625, 16384, 16384, 16384, 16384, 16384,
                                16384, 16384, 16384, 16384, 16384, 16384, 16384, 16384};

__global__ __launch_bounds__(BT, 1)
void hashenc_kernel(const float* __restrict__ x,
                    const float* __restrict__ emb,
                    int npts, int ppb)
{
    const int level    = blockIdx.x;
    const int res      = c_res[level];
    const int nenc     = c_nenc[level];
    const bool hashing = (level >= 3);

    extern __shared__ __half2 tab[];
    const float2* src = reinterpret_cast<const float2*>(emb) + level * TBL;
    for (int i = threadIdx.x; i < nenc; i += BT) {
        const float2 v = __ldg(src + i);
        tab[i] = __floats2half2_rn(v.x * SC, v.y * SC);   // scale folded in
    }
    __syncthreads();

    const float resf = (float)res;
    const int b0 = blockIdx.y * ppb;
    const int b1 = min(npts, b0 + ppb);
    __half2* scr = g_scr + (size_t)level * npts;

    for (int b = b0 + (int)threadIdx.x; b < b1; b += BT) {
        const float px = x[3 * b + 0];
        const float py = x[3 * b + 1];
        const float pz = x[3 * b + 2];

        const float sx = (px + 1.0f) * resf * 0.5f - 0.5f;
        const float sy = (py + 1.0f) * resf * 0.5f - 0.5f;
        const float sz = (pz + 1.0f) * resf * 0.5f - 0.5f;
        const float flx = floorf(sx), fly = floorf(sy), flz = floorf(sz);
        const float fx = sx - flx, fy = sy - fly, fz = sz - flz;
        const int cx = (int)flx, cy = (int)fly, cz = (int)flz;

        const float wx0 = (cx >= 0)       ? 1.0f - fx : 0.0f;
        const float wx1 = (cx <  res - 1) ? fx        : 0.0f;
        const float wy0 = (cy >= 0)       ? 1.0f - fy : 0.0f;
        const float wy1 = (cy <  res - 1) ? fy        : 0.0f;
        const float wz0 = (cz >= 0)       ? 1.0f - fz : 0.0f;
        const float wz1 = (cz <  res - 1) ? fz        : 0.0f;

        const float w00 = wx0 * wy0, w01 = wx0 * wy1;
        const float w10 = wx1 * wy0, w11 = wx1 * wy1;

        unsigned id[8];
        if (hashing) {
            const unsigned hx0 = (unsigned)cx;
            const unsigned hx1 = (unsigned)(cx + 1);
            const unsigned hy0 = (unsigned)cy       * 2654435761u;
            const unsigned hy1 = (unsigned)(cy + 1) * 2654435761u;
            const unsigned hz0 = (unsigned)cz       * 805459861u;
            const unsigned hz1 = (unsigned)(cz + 1) * 805459861u;
            const unsigned g00 = hx0 ^ hy0, g01 = hx0 ^ hy1;
            const unsigned g10 = hx1 ^ hy0, g11 = hx1 ^ hy1;
            const unsigned m = (unsigned)(nenc - 1);
            id[0] = (g00 ^ hz0) & m;  id[1] = (g00 ^ hz1) & m;
            id[2] = (g01 ^ hz0) & m;  id[3] = (g01 ^ hz1) & m;
            id[4] = (g10 ^ hz0) & m;  id[5] = (g10 ^ hz1) & m;
            id[6] = (g11 ^ hz0) & m;  id[7] = (g11 ^ hz1) & m;
        } else {
            const int r2 = res * res;
            const int a0 = cx,        a1 = cx + 1;
            const int b0v = cy * res, b1v = (cy + 1) * res;
            const int c0v = cz * r2,  c1v = (cz + 1) * r2;
            const unsigned lim = (unsigned)(nenc - 1);
            id[0] = min((unsigned)(a0 + b0v + c0v), lim);
            id[1] = min((unsigned)(a0 + b0v + c1v), lim);
            id[2] = min((unsigned)(a0 + b1v + c0v), lim);
            id[3] = min((unsigned)(a0 + b1v + c1v), lim);
            id[4] = min((unsigned)(a1 + b0v + c0v), lim);
            id[5] = min((unsigned)(a1 + b0v + c1v), lim);
            id[6] = min((unsigned)(a1 + b1v + c0v), lim);
            id[7] = min((unsigned)(a1 + b1v + c1v), lim);
        }

        const float w[8] = { w00 * wz0, w00 * wz1, w01 * wz0, w01 * wz1,
                             w10 * wz0, w10 * wz1, w11 * wz0, w11 * wz1 };

        float ax = 0.0f, ay = 0.0f;
        #pragma unroll
        for (int k = 0; k < 8; k++) {
            const float2 e = __half22float2(tab[id[k]]);   // LDS.32 gather
            ax = fmaf(w[k], e.x, ax);
            ay = fmaf(w[k], e.y, ay);
        }

        // already scaled (table carried x8192)
        scr[b] = __floats2half2_rn(ax, ay);
    }
}

// (L,B) half2 -> (B,16,2) fp32. Tile 512 points. Row stride 514 half2:
// conflict-free in both phases.
#define TPP 512
#define KT  256
#define TSTR 514

__global__ __launch_bounds__(KT)
void transpose_kernel(float4* __restrict__ out, int npts)
{
    __shared__ __half2 tile[NLV * TSTR];

    const int b0 = blockIdx.x * TPP;
    const int t  = threadIdx.x;
    const bool full = (b0 + TPP <= npts);

    if (full) {
        #pragma unroll 4
        for (int idx = t; idx < NLV * (TPP / 4); idx += KT) {
            const int l = idx >> 7;
            const int j = idx & 127;
            const uint4 v = *reinterpret_cast<const uint4*>(
                &g_scr[(size_t)l * npts + b0 + 4 * j]);
            uint2* dst = reinterpret_cast<uint2*>(&tile[l * TSTR + 4 * j]);
            dst[0] = make_uint2(v.x, v.y);
            dst[1] = make_uint2(v.z, v.w);
        }
    } else {
        for (int idx = t; idx < NLV * TPP; idx += KT) {
            const int l = idx >> 9;
            const int p = idx & (TPP - 1);
            tile[l * TSTR + p] = (b0 + p < npts)
                ? g_scr[(size_t)l * npts + b0 + p]
                : __floats2half2_rn(0.f, 0.f);
        }
    }
    __syncthreads();

    float4* obase = out + (size_t)b0 * 8;
    #pragma unroll 4
    for (int i = t; i < TPP * 8; i += KT) {
        const int p  = i >> 3;
        const int jp = i & 7;
        if (full || b0 + p < npts) {
            const float2 e0 = __half22float2(tile[(2 * jp)     * TSTR + p]);
            const float2 e1 = __half22float2(tile[(2 * jp + 1) * TSTR + p]);
            obase[i] = make_float4(e0.x * SCI, e0.y * SCI, e1.x * SCI, e1.y * SCI);
        }
    }
}

extern "C" void kernel_launch(void* const* d_in, const int* in_sizes, int n_in,
                              void* d_out, int out_size)
{
    const float* x   = (const float*)d_in[0];   // (B, 3) float32
    const float* emb = (const float*)d_in[1];   // (16, 16384, 2) float32
    float4* out      = (float4*)d_out;          // (B, 16, 2) float32

    const int npts = in_sizes[0] / 3;
    const int ppb  = (npts + NCHUNK - 1) / NCHUNK;
    const int smem = TBL * (int)sizeof(__half2); // 64 KB

    cudaFuncSetAttribute(hashenc_kernel,
                         cudaFuncAttributeMaxDynamicSharedMemorySize, smem);

    hashenc_kernel<<<dim3(NLV, NCHUNK), BT, smem>>>(x, emb, npts, ppb);
    transpose_kernel<<<(npts + TPP - 1) / TPP, KT>>>(out, npts);
}

// round 11
// speedup vs baseline: 2.7524x; 1.3503x over previous
#include <cuda_runtime.h>
#include <cuda_fp16.h>

// Round 11: two levels per block (2 x 64KB fp16 tables = 128KB smem) so each
// x read (9 wf) serves 2 point-levels; grid (8,37) = 296 blocks = exactly
// 2 waves. K2: KT 256->512 (full-thread occupancy) + streaming ld/st hints.

#define NLV 16
#define TBL 16384
#define BT  1024           // 32 warps, 1 CTA/SM
#define NCHUNK 37
#define MAXB 1048576
#define SC   8192.0f
#define SCI  (1.0f / 8192.0f)

__device__ __half2 g_scr[NLV * MAXB];   // 64 MB, layout (level, point)

__constant__ int c_res[NLV]  = {16, 20, 25, 32, 40, 50, 64, 80,
                                101, 128, 161, 203, 256, 322, 406, 512};
__constant__ int c_nenc[NLV] = {4096, 8000, 15625, 16384, 16384, 16384, 16384, 16384,
                                16384, 16384, 16384, 16384, 16384, 16384, 16384, 16384};

__device__ __forceinline__ void level_compute(
    float px, float py, float pz, int res, int nenc, bool hashing,
    const __half2* __restrict__ tab, __half2* __restrict__ scr, int b)
{
    const float resf = (float)res;
    const float sx = (px + 1.0f) * resf * 0.5f - 0.5f;
    const float sy = (py + 1.0f) * resf * 0.5f - 0.5f;
    const float sz = (pz + 1.0f) * resf * 0.5f - 0.5f;
    const float flx = floorf(sx), fly = floorf(sy), flz = floorf(sz);
    const float fx = sx - flx, fy = sy - fly, fz = sz - flz;
    const int cx = (int)flx, cy = (int)fly, cz = (int)flz;

    const float wx0 = (cx >= 0)       ? 1.0f - fx : 0.0f;
    const float wx1 = (cx <  res - 1) ? fx        : 0.0f;
    const float wy0 = (cy >= 0)       ? 1.0f - fy : 0.0f;
    const float wy1 = (cy <  res - 1) ? fy        : 0.0f;
    const float wz0 = (cz >= 0)       ? 1.0f - fz : 0.0f;
    const float wz1 = (cz <  res - 1) ? fz        : 0.0f;

    const float w00 = wx0 * wy0, w01 = wx0 * wy1;
    const float w10 = wx1 * wy0, w11 = wx1 * wy1;

    unsigned id[8];
    if (hashing) {
        const unsigned hx0 = (unsigned)cx;
        const unsigned hx1 = (unsigned)(cx + 1);
        const unsigned hy0 = (unsigned)cy       * 2654435761u;
        const unsigned hy1 = (unsigned)(cy + 1) * 2654435761u;
        const unsigned hz0 = (unsigned)cz       * 805459861u;
        const unsigned hz1 = (unsigned)(cz + 1) * 805459861u;
        const unsigned g00 = hx0 ^ hy0, g01 = hx0 ^ hy1;
        const unsigned g10 = hx1 ^ hy0, g11 = hx1 ^ hy1;
        const unsigned m = (unsigned)(nenc - 1);
        id[0] = (g00 ^ hz0) & m;  id[1] = (g00 ^ hz1) & m;
        id[2] = (g01 ^ hz0) & m;  id[3] = (g01 ^ hz1) & m;
        id[4] = (g10 ^ hz0) & m;  id[5] = (g10 ^ hz1) & m;
        id[6] = (g11 ^ hz0) & m;  id[7] = (g11 ^ hz1) & m;
    } else {
        const int r2 = res * res;
        const int a0 = cx,        a1 = cx + 1;
        const int b0v = cy * res, b1v = (cy + 1) * res;
        const int c0v = cz * r2,  c1v = (cz + 1) * r2;
        const unsigned lim = (unsigned)(nenc - 1);
        id[0] = min((unsigned)(a0 + b0v + c0v), lim);
        id[1] = min((unsigned)(a0 + b0v + c1v), lim);
        id[2] = min((unsigned)(a0 + b1v + c0v), lim);
        id[3] = min((unsigned)(a0 + b1v + c1v), lim);
        id[4] = min((unsigned)(a1 + b0v + c0v), lim);
        id[5] = min((unsigned)(a1 + b0v + c1v), lim);
        id[6] = min((unsigned)(a1 + b1v + c0v), lim);
        id[7] = min((unsigned)(a1 + b1v + c1v), lim);
    }

    const float w[8] = { w00 * wz0, w00 * wz1, w01 * wz0, w01 * wz1,
                         w10 * wz0, w10 * wz1, w11 * wz0, w11 * wz1 };

    float ax = 0.0f, ay = 0.0f;
    #pragma unroll
    for (int k = 0; k < 8; k++) {
        const float2 e = __half22float2(tab[id[k]]);   // LDS.32 gather
        ax = fmaf(w[k], e.x, ax);
        ay = fmaf(w[k], e.y, ay);
    }

    scr[b] = __floats2half2_rn(ax, ay);   // table carries the x8192 scale
}

__global__ __launch_bounds__(BT, 1)
void hashenc_kernel(const float* __restrict__ x,
                    const float* __restrict__ emb,
                    int npts, int ppb)
{
    const int pair = blockIdx.x;          // 0..7
    const int lA = 2 * pair, lB = 2 * pair + 1;
    const int resA = c_res[lA],  resB = c_res[lB];
    const int neA  = c_nenc[lA], neB  = c_nenc[lB];
    const bool hA = (lA >= 3), hB = (lB >= 3);

    extern __shared__ __half2 tab[];
    __half2* tabA = tab;
    __half2* tabB = tab + TBL;
    {
        const float2* srcA = reinterpret_cast<const float2*>(emb) + lA * TBL;
        const float2* srcB = reinterpret_cast<const float2*>(emb) + lB * TBL;
        for (int i = threadIdx.x; i < neA; i += BT) {
            const float2 v = __ldg(srcA + i);
            tabA[i] = __floats2half2_rn(v.x * SC, v.y * SC);
        }
        for (int i = threadIdx.x; i < neB; i += BT) {
            const float2 v = __ldg(srcB + i);
            tabB[i] = __floats2half2_rn(v.x * SC, v.y * SC);
        }
    }
    __syncthreads();

    const int b0 = blockIdx.y * ppb;
    const int b1 = min(npts, b0 + ppb);
    __half2* scrA = g_scr + (size_t)lA * npts;
    __half2* scrB = g_scr + (size_t)lB * npts;

    for (int b = b0 + (int)threadIdx.x; b < b1; b += BT) {
        const float px = x[3 * b + 0];
        const float py = x[3 * b + 1];
        const float pz = x[3 * b + 2];
        level_compute(px, py, pz, resA, neA, hA, tabA, scrA, b);
        level_compute(px, py, pz, resB, neB, hB, tabB, scrB, b);
    }
}

// (L,B) half2 -> (B,16,2) fp32. Tile 512 points, 512 threads (4 CTAs/SM).
// Smem row stride 514 half2: conflict-free in both phases.
#define TPP 512
#define KT  512
#define TSTR 514

__global__ __launch_bounds__(KT)
void transpose_kernel(float4* __restrict__ out, int npts)
{
    __shared__ __half2 tile[NLV * TSTR];

    const int b0 = blockIdx.x * TPP;
    const int t  = threadIdx.x;
    const bool full = (b0 + TPP <= npts);

    if (full) {
        #pragma unroll
        for (int idx = t; idx < NLV * (TPP / 4); idx += KT) {
            const int l = idx >> 7;
            const int j = idx & 127;
            const uint4 v = __ldcs(reinterpret_cast<const uint4*>(
                &g_scr[(size_t)l * npts + b0 + 4 * j]));
            uint2* dst = reinterpret_cast<uint2*>(&tile[l * TSTR + 4 * j]);
            dst[0] = make_uint2(v.x, v.y);
            dst[1] = make_uint2(v.z, v.w);
        }
    } else {
        for (int idx = t; idx < NLV * TPP; idx += KT) {
            const int l = idx >> 9;
            const int p = idx & (TPP - 1);
            tile[l * TSTR + p] = (b0 + p < npts)
                ? g_scr[(size_t)l * npts + b0 + p]
                : __floats2half2_rn(0.f, 0.f);
        }
    }
    __syncthreads();

    float4* obase = out + (size_t)b0 * 8;
    #pragma unroll
    for (int i = t; i < TPP * 8; i += KT) {
        const int p  = i >> 3;
        const int jp = i & 7;
        if (full || b0 + p < npts) {
            const float2 e0 = __half22float2(tile[(2 * jp)     * TSTR + p]);
            const float2 e1 = __half22float2(tile[(2 * jp + 1) * TSTR + p]);
            __stcs(&obase[i],
                   make_float4(e0.x * SCI, e0.y * SCI, e1.x * SCI, e1.y * SCI));
        }
    }
}

extern "C" void kernel_launch(void* const* d_in, const int* in_sizes, int n_in,
                              void* d_out, int out_size)
{
    const float* x   = (const float*)d_in[0];   // (B, 3) float32
    const float* emb = (const float*)d_in[1];   // (16, 16384, 2) float32
    float4* out      = (float4*)d_out;          // (B, 16, 2) float32

    const int npts = in_sizes[0] / 3;
    const int ppb  = (npts + NCHUNK - 1) / NCHUNK;
    const int smem = 2 * TBL * (int)sizeof(__half2); // 128 KB (two tables)

    cudaFuncSetAttribute(hashenc_kernel,
                         cudaFuncAttributeMaxDynamicSharedMemorySize, smem);

    hashenc_kernel<<<dim3(NLV / 2, NCHUNK), BT, smem>>>(x, emb, npts, ppb);
    transpose_kernel<<<(npts + TPP - 1) / TPP, KT>>>(out, npts);
}